// round 2
// baseline (speedup 1.0000x reference)
#include <cuda_runtime.h>
#include <math.h>

#define N_NODES 100000
#define E_MAX   1600000
#define FULL    0xffffffffu

// ---------------- scratch (static __device__ — no dynamic alloc) ----------------
__device__ int   g_deg[N_NODES + 1];
__device__ int   g_off[N_NODES + 1];
__device__ int   g_cur[N_NODES];
__device__ int   g_csr[E_MAX];

__device__ float g_xl1[N_NODES * 128];  // x @ W1
__device__ float g_as1[N_NODES * 8];    // a_src layer1
__device__ float g_ad1[N_NODES * 8];    // a_dst layer1
__device__ float g_h  [N_NODES * 128];  // elu(gat1 out)
__device__ float g_xl2[N_NODES * 64];   // h @ W2
__device__ float g_as2[N_NODES];
__device__ float g_ad2[N_NODES];

__device__ __forceinline__ float lrelu(float x) { return x > 0.f ? x : 0.2f * x; }
__device__ __forceinline__ float elu_f(float x) { return x > 0.f ? x : expm1f(x); }

// ---------------- CSR build ----------------
__global__ void k_zero() {
    int i = blockIdx.x * blockDim.x + threadIdx.x;
    if (i <= N_NODES) g_deg[i] = 0;
}

__global__ void k_hist(const int* __restrict__ ei, int E) {
    int e = blockIdx.x * blockDim.x + threadIdx.x;
    if (e < E) atomicAdd(&g_deg[ei[E + e]], 1);
}

// single-block exclusive scan over g_deg -> g_off, g_cur
__global__ void k_scan() {
    __shared__ int warp_sums[32];
    __shared__ int s_carry;
    int tid = threadIdx.x, lane = tid & 31, wid = tid >> 5;
    if (tid == 0) s_carry = 0;
    __syncthreads();
    for (int base = 0; base < N_NODES; base += 1024) {
        int i = base + tid;
        int v = (i < N_NODES) ? g_deg[i] : 0;
        int x = v;
        #pragma unroll
        for (int o = 1; o < 32; o <<= 1) {
            int t = __shfl_up_sync(FULL, x, o);
            if (lane >= o) x += t;
        }
        if (lane == 31) warp_sums[wid] = x;
        __syncthreads();
        if (wid == 0) {
            int ws = warp_sums[lane];
            #pragma unroll
            for (int o = 1; o < 32; o <<= 1) {
                int t = __shfl_up_sync(FULL, ws, o);
                if (lane >= o) ws += t;
            }
            warp_sums[lane] = ws;
        }
        __syncthreads();
        int incl = x + (wid > 0 ? warp_sums[wid - 1] : 0);
        int excl = s_carry + incl - v;
        if (i < N_NODES) { g_off[i] = excl; g_cur[i] = excl; }
        __syncthreads();
        if (tid == 1023) s_carry += incl;
        __syncthreads();
    }
    if (tid == 0) g_off[N_NODES] = s_carry;
}

__global__ void k_scatter(const int* __restrict__ ei, int E) {
    int e = blockIdx.x * blockDim.x + threadIdx.x;
    if (e < E) {
        int dst = ei[E + e];
        int p = atomicAdd(&g_cur[dst], 1);
        g_csr[p] = ei[e];
    }
}

// ---------------- GEMMs ----------------
// xl1[N,128] = x[N,128] @ W1[128,128]; 8 rows per block, 128 threads (1 col each)
__global__ void __launch_bounds__(128) k_gemm1(const float* __restrict__ x,
                                               const float* __restrict__ W) {
    __shared__ float sx[8][128];
    int c = threadIdx.x;
    int row0 = blockIdx.x * 8;
    #pragma unroll
    for (int r = 0; r < 8; r++) sx[r][c] = x[(row0 + r) * 128 + c];
    __syncthreads();
    float acc[8];
    #pragma unroll
    for (int r = 0; r < 8; r++) acc[r] = 0.f;
    #pragma unroll 4
    for (int k = 0; k < 128; k++) {
        float w = W[k * 128 + c];
        #pragma unroll
        for (int r = 0; r < 8; r++) acc[r] += sx[r][k] * w;
    }
    #pragma unroll
    for (int r = 0; r < 8; r++) g_xl1[(row0 + r) * 128 + c] = acc[r];
}

// xl2[N,64] = g_h[N,128] @ W2[128,64]; 8 rows per block, 64 threads
__global__ void __launch_bounds__(64) k_gemm2(const float* __restrict__ W) {
    __shared__ float sx[8 * 128];
    int c = threadIdx.x;
    int row0 = blockIdx.x * 8;
    for (int i = c; i < 8 * 128; i += 64) sx[i] = g_h[row0 * 128 + i];
    __syncthreads();
    float acc[8];
    #pragma unroll
    for (int r = 0; r < 8; r++) acc[r] = 0.f;
    #pragma unroll 4
    for (int k = 0; k < 128; k++) {
        float w = W[k * 64 + c];
        #pragma unroll
        for (int r = 0; r < 8; r++) acc[r] += sx[r * 128 + k] * w;
    }
    #pragma unroll
    for (int r = 0; r < 8; r++) g_xl2[(row0 + r) * 64 + c] = acc[r];
}

// ---------------- attention logits ----------------
// a_src1[n,h] = dot(xl1[n, h*16 : h*16+16], att_src1[h]); same for dst
__global__ void k_att1(const float* __restrict__ as, const float* __restrict__ ad) {
    int t = blockIdx.x * blockDim.x + threadIdx.x;
    if (t >= N_NODES * 8) return;
    int n = t >> 3, h = t & 7;
    const float4* xr = (const float4*)&g_xl1[n * 128 + h * 16];
    const float4* sv = (const float4*)&as[h * 16];
    const float4* dv = (const float4*)&ad[h * 16];
    float s = 0.f, d = 0.f;
    #pragma unroll
    for (int i = 0; i < 4; i++) {
        float4 xv = xr[i], a = sv[i], b = dv[i];
        s += xv.x * a.x + xv.y * a.y + xv.z * a.z + xv.w * a.w;
        d += xv.x * b.x + xv.y * b.y + xv.z * b.z + xv.w * b.w;
    }
    g_as1[t] = s;
    g_ad1[t] = d;
}

__global__ void k_att2(const float* __restrict__ as, const float* __restrict__ ad) {
    int n = blockIdx.x * blockDim.x + threadIdx.x;
    if (n >= N_NODES) return;
    const float4* xr = (const float4*)&g_xl2[n * 64];
    const float4* sv = (const float4*)as;
    const float4* dv = (const float4*)ad;
    float s = 0.f, d = 0.f;
    #pragma unroll
    for (int i = 0; i < 16; i++) {
        float4 xv = xr[i], a = sv[i], b = dv[i];
        s += xv.x * a.x + xv.y * a.y + xv.z * a.z + xv.w * a.w;
        d += xv.x * b.x + xv.y * b.y + xv.z * b.z + xv.w * b.w;
    }
    g_as2[n] = s;
    g_ad2[n] = d;
}

// ---------------- layer-1 aggregation: one warp per destination ----------------
__global__ void __launch_bounds__(256) k_agg1(const float* __restrict__ b1) {
    int gw = (blockIdx.x * blockDim.x + threadIdx.x) >> 5;
    if (gw >= N_NODES) return;
    int lane = threadIdx.x & 31;
    int dst = gw;
    int beg = g_off[dst], end = g_off[dst + 1];
    int h = lane & 7;
    float adst = g_ad1[dst * 8 + h];
    float e_self = lrelu(g_as1[dst * 8 + h] + adst);

    // online softmax: 4 edge-groups x 8 heads across the warp
    float m = -1e30f, s = 0.f;
    for (int i = beg + (lane >> 3); i < end; i += 4) {
        int src = g_csr[i];
        float e = lrelu(g_as1[src * 8 + h] + adst);
        float nm = fmaxf(m, e);
        s = s * __expf(m - nm) + __expf(e - nm);
        m = nm;
    }
    #pragma unroll
    for (int ofs = 8; ofs < 32; ofs <<= 1) {
        float mo = __shfl_xor_sync(FULL, m, ofs);
        float so = __shfl_xor_sync(FULL, s, ofs);
        float nm = fmaxf(m, mo);
        s = s * __expf(m - nm) + so * __expf(mo - nm);
        m = nm;
    }
    float M = fmaxf(m, e_self);
    float S = s * __expf(m - M) + __expf(e_self - M);
    float invS = 1.f / (S + 1e-16f);
    float wself = __expf(e_self - M) * invS;   // valid for head h = lane&7

    int col = lane << 2;       // 4 features per lane
    int hs = lane >> 2;        // head index of this lane's features
    // FIX: features at col belong to head hs, so the self-loop weight must be
    // fetched from the lane holding head hs (lane hs itself, since lanes 0..7
    // carry heads 0..7).
    float wself_sel = __shfl_sync(FULL, wself, hs);
    float4 xv = *(const float4*)&g_xl1[dst * 128 + col];
    float4 acc = make_float4(wself_sel * xv.x, wself_sel * xv.y,
                             wself_sel * xv.z, wself_sel * xv.w);

    for (int base = beg; base < end; base += 32) {
        int mysrc = 0;
        if (base + lane < end) mysrc = g_csr[base + lane];
        int cnt = min(32, end - base);
        for (int j = 0; j < cnt; j++) {
            int src = __shfl_sync(FULL, mysrc, j);
            float e = lrelu(g_as1[src * 8 + h] + adst);
            float w = __expf(e - M) * invS;
            float wsel = __shfl_sync(FULL, w, hs);
            float4 v = *(const float4*)&g_xl1[src * 128 + col];
            acc.x += wsel * v.x;
            acc.y += wsel * v.y;
            acc.z += wsel * v.z;
            acc.w += wsel * v.w;
        }
    }
    float4 o;
    o.x = elu_f(acc.x + b1[col + 0]);
    o.y = elu_f(acc.y + b1[col + 1]);
    o.z = elu_f(acc.z + b1[col + 2]);
    o.w = elu_f(acc.w + b1[col + 3]);
    *(float4*)&g_h[dst * 128 + col] = o;
}

// ---------------- layer-2 aggregation (H=1, C=64): one warp per destination ----------------
__global__ void __launch_bounds__(256) k_agg2(const float* __restrict__ b2,
                                              float* __restrict__ out) {
    int gw = (blockIdx.x * blockDim.x + threadIdx.x) >> 5;
    if (gw >= N_NODES) return;
    int lane = threadIdx.x & 31;
    int dst = gw;
    int beg = g_off[dst], end = g_off[dst + 1];
    float adst = g_ad2[dst];
    float e_self = lrelu(g_as2[dst] + adst);

    float m = -1e30f, s = 0.f;
    for (int i = beg + lane; i < end; i += 32) {
        int src = g_csr[i];
        float e = lrelu(g_as2[src] + adst);
        float nm = fmaxf(m, e);
        s = s * __expf(m - nm) + __expf(e - nm);
        m = nm;
    }
    #pragma unroll
    for (int ofs = 1; ofs < 32; ofs <<= 1) {
        float mo = __shfl_xor_sync(FULL, m, ofs);
        float so = __shfl_xor_sync(FULL, s, ofs);
        float nm = fmaxf(m, mo);
        s = s * __expf(m - nm) + so * __expf(mo - nm);
        m = nm;
    }
    float M = fmaxf(m, e_self);
    float S = s * __expf(m - M) + __expf(e_self - M);
    float invS = 1.f / (S + 1e-16f);
    float wself = __expf(e_self - M) * invS;   // H=1: identical on all lanes

    int half = lane >> 4, l16 = lane & 15, col = l16 << 2;
    float4 acc = make_float4(0.f, 0.f, 0.f, 0.f);
    if (half == 0) {
        float4 xv = *(const float4*)&g_xl2[dst * 64 + col];
        acc = make_float4(wself * xv.x, wself * xv.y, wself * xv.z, wself * xv.w);
    }
    for (int i = beg + half; i < end; i += 2) {
        int src = g_csr[i];
        float e = lrelu(g_as2[src] + adst);
        float w = __expf(e - M) * invS;
        float4 v = *(const float4*)&g_xl2[src * 64 + col];
        acc.x += w * v.x;
        acc.y += w * v.y;
        acc.z += w * v.z;
        acc.w += w * v.w;
    }
    acc.x += __shfl_xor_sync(FULL, acc.x, 16);
    acc.y += __shfl_xor_sync(FULL, acc.y, 16);
    acc.z += __shfl_xor_sync(FULL, acc.z, 16);
    acc.w += __shfl_xor_sync(FULL, acc.w, 16);
    if (half == 0) {
        float4 o;
        o.x = acc.x + b2[col + 0];
        o.y = acc.y + b2[col + 1];
        o.z = acc.z + b2[col + 2];
        o.w = acc.w + b2[col + 3];
        *(float4*)&out[dst * 64 + col] = o;
    }
}

// ---------------- launch ----------------
extern "C" void kernel_launch(void* const* d_in, const int* in_sizes, int n_in,
                              void* d_out, int out_size) {
    const float* x   = (const float*)d_in[0];
    const int*   ei  = (const int*)d_in[1];
    const float* W1  = (const float*)d_in[2];
    const float* as1 = (const float*)d_in[3];
    const float* ad1 = (const float*)d_in[4];
    const float* b1  = (const float*)d_in[5];
    const float* W2  = (const float*)d_in[6];
    const float* as2 = (const float*)d_in[7];
    const float* ad2 = (const float*)d_in[8];
    const float* b2  = (const float*)d_in[9];
    float* out = (float*)d_out;
    int E = in_sizes[1] / 2;

    // CSR build (dst-sorted)
    k_zero<<<(N_NODES + 256) / 256, 256>>>();
    k_hist<<<(E + 255) / 256, 256>>>(ei, E);
    k_scan<<<1, 1024>>>();
    k_scatter<<<(E + 255) / 256, 256>>>(ei, E);

    // layer 1
    k_gemm1<<<N_NODES / 8, 128>>>(x, W1);
    k_att1<<<(N_NODES * 8 + 255) / 256, 256>>>(as1, ad1);
    k_agg1<<<N_NODES / 8, 256>>>(b1);   // 1 warp per node, 8 warps/block

    // layer 2
    k_gemm2<<<N_NODES / 8, 64>>>(W2);
    k_att2<<<(N_NODES + 255) / 256, 256>>>(as2, ad2);
    k_agg2<<<N_NODES / 8, 256>>>(b2, out);
}

// round 3
// speedup vs baseline: 1.1206x; 1.1206x over previous
#include <cuda_runtime.h>
#include <math.h>

#define N_NODES 100000
#define E_MAX   1600000
#define FULL    0xffffffffu

// ---------------- scratch (static __device__ — no dynamic alloc) ----------------
__device__ int   g_deg[N_NODES + 4];
__device__ int   g_off[N_NODES + 4];
__device__ int   g_cur[N_NODES + 4];
__device__ int   g_csr[E_MAX];

__device__ float g_xl1[N_NODES * 128];  // x @ W1
__device__ float g_as1[N_NODES * 8];    // a_src layer1
__device__ float g_ad1[N_NODES * 8];    // a_dst layer1
__device__ float g_h  [N_NODES * 128];  // elu(gat1 out)
__device__ float g_xl2[N_NODES * 64];   // h @ W2
__device__ float g_as2[N_NODES];
__device__ float g_ad2[N_NODES];

__device__ __forceinline__ float lrelu(float x) { return x > 0.f ? x : 0.2f * x; }
__device__ __forceinline__ float elu_f(float x) { return x > 0.f ? x : expm1f(x); }

// packed f32x2 helpers (FFMA2 — PTX-only, doubles fp32 FMA throughput on sm_103a)
__device__ __forceinline__ unsigned long long pk2(float lo, float hi) {
    unsigned long long r;
    asm("mov.b64 %0, {%1, %2};" : "=l"(r) : "f"(lo), "f"(hi));
    return r;
}
__device__ __forceinline__ void upk2(unsigned long long v, float& lo, float& hi) {
    asm("mov.b64 {%0, %1}, %2;" : "=f"(lo), "=f"(hi) : "l"(v));
}
__device__ __forceinline__ unsigned long long fma2(unsigned long long a,
                                                   unsigned long long b,
                                                   unsigned long long c) {
    unsigned long long d;
    asm("fma.rn.f32x2 %0, %1, %2, %3;" : "=l"(d) : "l"(a), "l"(b), "l"(c));
    return d;
}

// ---------------- CSR build ----------------
__global__ void k_zero() {
    int i = blockIdx.x * blockDim.x + threadIdx.x;
    if (i < N_NODES + 4) g_deg[i] = 0;
}

__global__ void k_hist(const int* __restrict__ ei, int E) {
    int t = blockIdx.x * blockDim.x + threadIdx.x;
    int n4 = E >> 2;
    const int4* d4 = (const int4*)(ei + E);
    if (t < n4) {
        int4 v = d4[t];
        atomicAdd(&g_deg[v.x], 1);
        atomicAdd(&g_deg[v.y], 1);
        atomicAdd(&g_deg[v.z], 1);
        atomicAdd(&g_deg[v.w], 1);
    } else if (t == n4) {
        for (int e = n4 * 4; e < E; e++) atomicAdd(&g_deg[ei[E + e]], 1);
    }
}

// single-block exclusive scan (int4-vectorized: 25 iterations)
__global__ void k_scan() {
    __shared__ int warp_sums[32];
    __shared__ int s_carry;
    int tid = threadIdx.x, lane = tid & 31, wid = tid >> 5;
    if (tid == 0) s_carry = 0;
    __syncthreads();
    const int4* deg4 = (const int4*)g_deg;
    int4* off4 = (int4*)g_off;
    int4* cur4 = (int4*)g_cur;
    const int N4 = N_NODES / 4;  // 25000
    for (int base = 0; base < N4; base += 1024) {
        int i = base + tid;
        int4 v = (i < N4) ? deg4[i] : make_int4(0, 0, 0, 0);
        int tot = v.x + v.y + v.z + v.w;
        int xs = tot;
        #pragma unroll
        for (int o = 1; o < 32; o <<= 1) {
            int t = __shfl_up_sync(FULL, xs, o);
            if (lane >= o) xs += t;
        }
        if (lane == 31) warp_sums[wid] = xs;
        __syncthreads();
        if (wid == 0) {
            int ws = warp_sums[lane];
            #pragma unroll
            for (int o = 1; o < 32; o <<= 1) {
                int t = __shfl_up_sync(FULL, ws, o);
                if (lane >= o) ws += t;
            }
            warp_sums[lane] = ws;
        }
        __syncthreads();
        int incl = xs + (wid > 0 ? warp_sums[wid - 1] : 0);
        int b0 = s_carry + incl - tot;
        if (i < N4) {
            int4 o;
            o.x = b0;
            o.y = b0 + v.x;
            o.z = o.y + v.y;
            o.w = o.z + v.z;
            off4[i] = o;
            cur4[i] = o;
        }
        int blk_total = warp_sums[31];
        __syncthreads();
        if (tid == 0) s_carry += blk_total;
        __syncthreads();
    }
    if (tid == 0) g_off[N_NODES] = s_carry;
}

__global__ void k_scatter(const int* __restrict__ ei, int E) {
    int t = blockIdx.x * blockDim.x + threadIdx.x;
    int n4 = E >> 2;
    const int4* s4 = (const int4*)ei;
    const int4* d4 = (const int4*)(ei + E);
    if (t < n4) {
        int4 s = s4[t];
        int4 d = d4[t];
        g_csr[atomicAdd(&g_cur[d.x], 1)] = s.x;
        g_csr[atomicAdd(&g_cur[d.y], 1)] = s.y;
        g_csr[atomicAdd(&g_cur[d.z], 1)] = s.z;
        g_csr[atomicAdd(&g_cur[d.w], 1)] = s.w;
    } else if (t == n4) {
        for (int e = n4 * 4; e < E; e++)
            g_csr[atomicAdd(&g_cur[ei[E + e]], 1)] = ei[e];
    }
}

// ---------------- GEMM1 + att1 fused ----------------
// xl1[N,128] = x @ W1; 32 rows/block, 128 threads (thread = out col), f32x2 packed rows.
// Epilogue computes a_src1/a_dst1 per (row, head) via 16-lane shuffle reductions.
__global__ void __launch_bounds__(128) k_gemm1att1(const float* __restrict__ x,
                                                   const float* __restrict__ W,
                                                   const float* __restrict__ asv,
                                                   const float* __restrict__ adv) {
    __shared__ float sxT[128][34];  // [k][row], pad keeps float2 align + low conflicts
    int c = threadIdx.x;
    int row0 = blockIdx.x * 32;
    #pragma unroll 8
    for (int r = 0; r < 32; r++)
        sxT[c][r] = x[(row0 + r) * 128 + c];
    __syncthreads();

    unsigned long long acc[16];
    #pragma unroll
    for (int i = 0; i < 16; i++) acc[i] = 0ull;

    #pragma unroll 4
    for (int k = 0; k < 128; k++) {
        float w = W[k * 128 + c];
        unsigned long long w2 = pk2(w, w);
        const float2* col2 = (const float2*)&sxT[k][0];
        #pragma unroll
        for (int i = 0; i < 16; i++) {
            float2 a = col2[i];
            acc[i] = fma2(pk2(a.x, a.y), w2, acc[i]);
        }
    }

    float as_c = asv[c], ad_c = adv[c];
    int head = c >> 4, l16 = c & 15;
    #pragma unroll
    for (int i = 0; i < 16; i++) {
        float o0, o1;
        upk2(acc[i], o0, o1);
        g_xl1[(row0 + 2 * i) * 128 + c] = o0;
        g_xl1[(row0 + 2 * i + 1) * 128 + c] = o1;
        float s0 = o0 * as_c, d0 = o0 * ad_c;
        float s1 = o1 * as_c, d1 = o1 * ad_c;
        #pragma unroll
        for (int ofs = 1; ofs < 16; ofs <<= 1) {
            s0 += __shfl_xor_sync(FULL, s0, ofs);
            d0 += __shfl_xor_sync(FULL, d0, ofs);
            s1 += __shfl_xor_sync(FULL, s1, ofs);
            d1 += __shfl_xor_sync(FULL, d1, ofs);
        }
        if (l16 == 0) {
            g_as1[(row0 + 2 * i) * 8 + head] = s0;
            g_ad1[(row0 + 2 * i) * 8 + head] = d0;
            g_as1[(row0 + 2 * i + 1) * 8 + head] = s1;
            g_ad1[(row0 + 2 * i + 1) * 8 + head] = d1;
        }
    }
}

// ---------------- GEMM2 + att2 fused ----------------
// xl2[N,64] = g_h @ W2; 32 rows/block, 64 threads, f32x2 packed rows.
__global__ void __launch_bounds__(64) k_gemm2att2(const float* __restrict__ W,
                                                  const float* __restrict__ asv,
                                                  const float* __restrict__ adv) {
    __shared__ float shT[128][34];
    __shared__ float red[2][32][2];
    int c = threadIdx.x;  // 0..63
    int row0 = blockIdx.x * 32;
    int k0 = c, k1 = c + 64;
    #pragma unroll 4
    for (int r = 0; r < 32; r++) {
        shT[k0][r] = g_h[(row0 + r) * 128 + k0];
        shT[k1][r] = g_h[(row0 + r) * 128 + k1];
    }
    __syncthreads();

    unsigned long long acc[16];
    #pragma unroll
    for (int i = 0; i < 16; i++) acc[i] = 0ull;

    #pragma unroll 4
    for (int k = 0; k < 128; k++) {
        float w = W[k * 64 + c];
        unsigned long long w2 = pk2(w, w);
        const float2* col2 = (const float2*)&shT[k][0];
        #pragma unroll
        for (int i = 0; i < 16; i++) {
            float2 a = col2[i];
            acc[i] = fma2(pk2(a.x, a.y), w2, acc[i]);
        }
    }

    float as_c = asv[c], ad_c = adv[c];
    int lane = c & 31, wrp = c >> 5;
    #pragma unroll
    for (int i = 0; i < 16; i++) {
        float o0, o1;
        upk2(acc[i], o0, o1);
        g_xl2[(row0 + 2 * i) * 64 + c] = o0;
        g_xl2[(row0 + 2 * i + 1) * 64 + c] = o1;
        float s0 = o0 * as_c, d0 = o0 * ad_c;
        float s1 = o1 * as_c, d1 = o1 * ad_c;
        #pragma unroll
        for (int ofs = 1; ofs < 32; ofs <<= 1) {
            s0 += __shfl_xor_sync(FULL, s0, ofs);
            d0 += __shfl_xor_sync(FULL, d0, ofs);
            s1 += __shfl_xor_sync(FULL, s1, ofs);
            d1 += __shfl_xor_sync(FULL, d1, ofs);
        }
        if (lane == 0) {
            red[wrp][2 * i][0] = s0;
            red[wrp][2 * i][1] = d0;
            red[wrp][2 * i + 1][0] = s1;
            red[wrp][2 * i + 1][1] = d1;
        }
    }
    __syncthreads();
    if (c < 32) {
        g_as2[row0 + c] = red[0][c][0] + red[1][c][0];
        g_ad2[row0 + c] = red[0][c][1] + red[1][c][1];
    }
}

// ---------------- layer-1 aggregation: one warp per node, SINGLE PASS ----------------
// Logits bounded (|e| < ~6) -> exp() without max-subtraction is safe; accumulate
// unnormalized numerator + denominator in one edge pass, divide at the end.
__global__ void __launch_bounds__(256) k_agg1(const float* __restrict__ b1) {
    int gw = (blockIdx.x * blockDim.x + threadIdx.x) >> 5;
    if (gw >= N_NODES) return;
    int lane = threadIdx.x & 31;
    int dst = gw;
    int beg = g_off[dst], end = g_off[dst + 1];
    int h = lane & 7, g = lane >> 3;
    int col = lane << 2, hs = lane >> 2;

    float adst = g_ad1[dst * 8 + h];
    float wself = __expf(lrelu(g_as1[dst * 8 + h] + adst));
    float denom = (g == 0) ? wself : 0.f;
    float wself_sel = __shfl_sync(FULL, wself, hs);
    float4 xv = *(const float4*)&g_xl1[dst * 128 + col];
    float4 acc = make_float4(wself_sel * xv.x, wself_sel * xv.y,
                             wself_sel * xv.z, wself_sel * xv.w);

    for (int base = beg; base < end; base += 32) {
        int mycsr = (base + lane < end) ? g_csr[base + lane] : 0;
        int n = min(32, end - base);
        for (int sub = 0; sub < n; sub += 4) {
            // 4 edges per step: group g computes weights for edge sub+g, head h
            int src_g = __shfl_sync(FULL, mycsr, sub + g);
            float e = lrelu(__ldg(&g_as1[src_g * 8 + h]) + adst);
            float w = ((sub + g) < n) ? __expf(e) : 0.f;
            denom += w;
            #pragma unroll
            for (int j = 0; j < 4; j++) {
                if (sub + j < n) {
                    int srcj = __shfl_sync(FULL, mycsr, sub + j);
                    float wsel = __shfl_sync(FULL, w, (j << 3) + hs);
                    float4 v = *(const float4*)&g_xl1[srcj * 128 + col];
                    acc.x += wsel * v.x;
                    acc.y += wsel * v.y;
                    acc.z += wsel * v.z;
                    acc.w += wsel * v.w;
                }
            }
        }
    }
    // sum denominators over the 4 edge-groups (same head)
    denom += __shfl_xor_sync(FULL, denom, 8);
    denom += __shfl_xor_sync(FULL, denom, 16);
    float invS = 1.f / (denom + 1e-16f);
    float invS_sel = __shfl_sync(FULL, invS, hs);

    float4 o;
    o.x = elu_f(acc.x * invS_sel + b1[col + 0]);
    o.y = elu_f(acc.y * invS_sel + b1[col + 1]);
    o.z = elu_f(acc.z * invS_sel + b1[col + 2]);
    o.w = elu_f(acc.w * invS_sel + b1[col + 3]);
    *(float4*)&g_h[dst * 128 + col] = o;
}

// ---------------- layer-2 aggregation (H=1, C=64): one warp per node, SINGLE PASS ----
__global__ void __launch_bounds__(256) k_agg2(const float* __restrict__ b2,
                                              float* __restrict__ out) {
    int gw = (blockIdx.x * blockDim.x + threadIdx.x) >> 5;
    if (gw >= N_NODES) return;
    int lane = threadIdx.x & 31;
    int q = lane >> 3;             // edge slot 0..3
    int col = (lane & 15) << 2;    // feature cols (halves duplicate)
    int dst = gw;
    int beg = g_off[dst], end = g_off[dst + 1];

    float adst = g_ad2[dst];
    float wself = __expf(lrelu(g_as2[dst] + adst));
    float denom = (q == 0) ? wself : 0.f;
    float4 xv = *(const float4*)&g_xl2[dst * 64 + col];
    float4 acc = make_float4(wself * xv.x, wself * xv.y, wself * xv.z, wself * xv.w);

    for (int base = beg; base < end; base += 32) {
        int mycsr = (base + lane < end) ? g_csr[base + lane] : 0;
        int n = min(32, end - base);
        for (int sub = 0; sub < n; sub += 4) {
            int src_q = __shfl_sync(FULL, mycsr, sub + q);
            float e = lrelu(__ldg(&g_as2[src_q]) + adst);
            float w = ((sub + q) < n) ? __expf(e) : 0.f;
            denom += w;
            #pragma unroll
            for (int j = 0; j < 4; j++) {
                if (sub + j < n) {
                    int srcj = __shfl_sync(FULL, mycsr, sub + j);
                    float wj = __shfl_sync(FULL, w, j << 3);
                    float4 v = *(const float4*)&g_xl2[srcj * 64 + col];
                    acc.x += wj * v.x;
                    acc.y += wj * v.y;
                    acc.z += wj * v.z;
                    acc.w += wj * v.w;
                }
            }
        }
    }
    denom += __shfl_xor_sync(FULL, denom, 8);
    denom += __shfl_xor_sync(FULL, denom, 16);
    float invS = 1.f / (denom + 1e-16f);

    if (lane < 16) {
        float4 o;
        o.x = acc.x * invS + b2[col + 0];
        o.y = acc.y * invS + b2[col + 1];
        o.z = acc.z * invS + b2[col + 2];
        o.w = acc.w * invS + b2[col + 3];
        *(float4*)&out[dst * 64 + col] = o;
    }
}

// ---------------- launch ----------------
extern "C" void kernel_launch(void* const* d_in, const int* in_sizes, int n_in,
                              void* d_out, int out_size) {
    const float* x   = (const float*)d_in[0];
    const int*   ei  = (const int*)d_in[1];
    const float* W1  = (const float*)d_in[2];
    const float* as1 = (const float*)d_in[3];
    const float* ad1 = (const float*)d_in[4];
    const float* b1  = (const float*)d_in[5];
    const float* W2  = (const float*)d_in[6];
    const float* as2 = (const float*)d_in[7];
    const float* ad2 = (const float*)d_in[8];
    const float* b2  = (const float*)d_in[9];
    float* out = (float*)d_out;
    int E = in_sizes[1] / 2;
    int n4t = (E >> 2) + 1;  // int4 threads + 1 tail thread

    k_gemm1att1<<<N_NODES / 32, 128>>>(x, W1, as1, ad1);          // 0
    k_zero<<<(N_NODES + 4 + 255) / 256, 256>>>();                 // 1
    k_hist<<<(n4t + 255) / 256, 256>>>(ei, E);                    // 2
    k_scan<<<1, 1024>>>();                                        // 3
    k_scatter<<<(n4t + 255) / 256, 256>>>(ei, E);                 // 4
    k_agg1<<<N_NODES / 8, 256>>>(b1);                             // 5
    k_gemm2att2<<<N_NODES / 32, 64>>>(W2, as2, ad2);              // 6
    k_agg2<<<N_NODES / 8, 256>>>(b2, out);                        // 7
}

// round 6
// speedup vs baseline: 1.2782x; 1.1407x over previous
#include <cuda_runtime.h>
#include <math.h>

#define N_NODES 100000
#define E_MAX   1600000
#define FULL    0xffffffffu
#define N4      (N_NODES / 4)        // 25000 int4 groups
#define SCAN_B  ((N4 + 1023) / 1024) // 25 scan blocks

// ---------------- scratch (static __device__ — no dynamic alloc) ----------------
__device__ int   g_deg[N_NODES + 4];
__device__ int   g_off[N_NODES + 4];
__device__ int   g_cur[N_NODES + 4];
__device__ int   g_csr[E_MAX];
__device__ int   g_blk[SCAN_B];
__device__ int   g_blkoff[SCAN_B];

__device__ float g_xl1[N_NODES * 128];  // x @ W1
__device__ float g_as1[N_NODES * 8];    // a_src layer1
__device__ float g_ad1[N_NODES * 8];    // a_dst layer1
__device__ float g_h  [N_NODES * 128];  // elu(gat1 out)
__device__ float g_xl2[N_NODES * 64];   // h @ W2
__device__ float g_as2[N_NODES];
__device__ float g_ad2[N_NODES];

__device__ __forceinline__ float lrelu(float x) { return x > 0.f ? x : 0.2f * x; }
__device__ __forceinline__ float elu_f(float x) { return x > 0.f ? x : expm1f(x); }

// packed f32x2 helpers (FFMA2 — PTX-only, doubles fp32 FMA throughput on sm_103a)
__device__ __forceinline__ unsigned long long pk2(float lo, float hi) {
    unsigned long long r;
    asm("mov.b64 %0, {%1, %2};" : "=l"(r) : "f"(lo), "f"(hi));
    return r;
}
__device__ __forceinline__ void upk2(unsigned long long v, float& lo, float& hi) {
    asm("mov.b64 {%0, %1}, %2;" : "=f"(lo), "=f"(hi) : "l"(v));
}
__device__ __forceinline__ unsigned long long fma2(unsigned long long a,
                                                   unsigned long long b,
                                                   unsigned long long c) {
    unsigned long long d;
    asm("fma.rn.f32x2 %0, %1, %2, %3;" : "=l"(d) : "l"(a), "l"(b), "l"(c));
    return d;
}

// ---------------- CSR build ----------------
__global__ void k_zero() {
    int i = blockIdx.x * blockDim.x + threadIdx.x;
    if (i < N_NODES + 4) g_deg[i] = 0;
}

__global__ void k_hist(const int* __restrict__ ei, int E) {
    int t = blockIdx.x * blockDim.x + threadIdx.x;
    int n4 = E >> 2;
    const int4* d4 = (const int4*)(ei + E);
    if (t < n4) {
        int4 v = d4[t];
        atomicAdd(&g_deg[v.x], 1);
        atomicAdd(&g_deg[v.y], 1);
        atomicAdd(&g_deg[v.z], 1);
        atomicAdd(&g_deg[v.w], 1);
    } else if (t == n4) {
        for (int e = n4 * 4; e < E; e++) atomicAdd(&g_deg[ei[E + e]], 1);
    }
}

// ---- multi-block scan: phase 1 — per-block exclusive scan + block totals ----
__global__ void __launch_bounds__(1024) k_scan1() {
    __shared__ int warp_sums[32];
    int tid = threadIdx.x, lane = tid & 31, wid = tid >> 5;
    int i = blockIdx.x * 1024 + tid;
    const int4* deg4 = (const int4*)g_deg;
    int4* off4 = (int4*)g_off;

    int4 v = (i < N4) ? deg4[i] : make_int4(0, 0, 0, 0);
    int tot = v.x + v.y + v.z + v.w;
    int xs = tot;
    #pragma unroll
    for (int o = 1; o < 32; o <<= 1) {
        int t = __shfl_up_sync(FULL, xs, o);
        if (lane >= o) xs += t;
    }
    if (lane == 31) warp_sums[wid] = xs;
    __syncthreads();
    if (wid == 0) {
        int ws = warp_sums[lane];
        #pragma unroll
        for (int o = 1; o < 32; o <<= 1) {
            int t = __shfl_up_sync(FULL, ws, o);
            if (lane >= o) ws += t;
        }
        warp_sums[lane] = ws;
    }
    __syncthreads();
    int incl = xs + (wid > 0 ? warp_sums[wid - 1] : 0);
    int b0 = incl - tot;
    if (i < N4) {
        int4 o;
        o.x = b0;
        o.y = b0 + v.x;
        o.z = o.y + v.y;
        o.w = o.z + v.z;
        off4[i] = o;
    }
    if (tid == 0) g_blk[blockIdx.x] = warp_sums[31];
}

// ---- scan phase 2: single warp scans the block totals ----
__global__ void k_scan2() {
    int lane = threadIdx.x;
    int t = (lane < SCAN_B) ? g_blk[lane] : 0;
    int xs = t;
    #pragma unroll
    for (int o = 1; o < 32; o <<= 1) {
        int u = __shfl_up_sync(FULL, xs, o);
        if (lane >= o) xs += u;
    }
    if (lane < SCAN_B) g_blkoff[lane] = xs - t;
    if (lane == 31) g_off[N_NODES] = xs;
}

// ---- scan phase 3: add block offsets, fill g_cur ----
__global__ void __launch_bounds__(1024) k_scan3() {
    int i = blockIdx.x * 1024 + threadIdx.x;
    if (i < N4) {
        int add = g_blkoff[i >> 10];
        int4* off4 = (int4*)g_off;
        int4* cur4 = (int4*)g_cur;
        int4 o = off4[i];
        o.x += add; o.y += add; o.z += add; o.w += add;
        off4[i] = o;
        cur4[i] = o;
    }
}

__global__ void k_scatter(const int* __restrict__ ei, int E) {
    int t = blockIdx.x * blockDim.x + threadIdx.x;
    int n4 = E >> 2;
    const int4* s4 = (const int4*)ei;
    const int4* d4 = (const int4*)(ei + E);
    if (t < n4) {
        int4 s = s4[t];
        int4 d = d4[t];
        g_csr[atomicAdd(&g_cur[d.x], 1)] = s.x;
        g_csr[atomicAdd(&g_cur[d.y], 1)] = s.y;
        g_csr[atomicAdd(&g_cur[d.z], 1)] = s.z;
        g_csr[atomicAdd(&g_cur[d.w], 1)] = s.w;
    } else if (t == n4) {
        for (int e = n4 * 4; e < E; e++)
            g_csr[atomicAdd(&g_cur[ei[E + e]], 1)] = ei[e];
    }
}

// ---------------- GEMM1 + att1 fused ----------------
__global__ void __launch_bounds__(128) k_gemm1att1(const float* __restrict__ x,
                                                   const float* __restrict__ W,
                                                   const float* __restrict__ asv,
                                                   const float* __restrict__ adv) {
    __shared__ float sxT[128][34];
    int c = threadIdx.x;
    int row0 = blockIdx.x * 32;
    #pragma unroll 8
    for (int r = 0; r < 32; r++)
        sxT[c][r] = x[(row0 + r) * 128 + c];
    __syncthreads();

    unsigned long long acc[16];
    #pragma unroll
    for (int i = 0; i < 16; i++) acc[i] = 0ull;

    #pragma unroll 4
    for (int k = 0; k < 128; k++) {
        float w = W[k * 128 + c];
        unsigned long long w2 = pk2(w, w);
        const float2* col2 = (const float2*)&sxT[k][0];
        #pragma unroll
        for (int i = 0; i < 16; i++) {
            float2 a = col2[i];
            acc[i] = fma2(pk2(a.x, a.y), w2, acc[i]);
        }
    }

    float as_c = asv[c], ad_c = adv[c];
    int head = c >> 4, l16 = c & 15;
    #pragma unroll
    for (int i = 0; i < 16; i++) {
        float o0, o1;
        upk2(acc[i], o0, o1);
        g_xl1[(row0 + 2 * i) * 128 + c] = o0;
        g_xl1[(row0 + 2 * i + 1) * 128 + c] = o1;
        float s0 = o0 * as_c, d0 = o0 * ad_c;
        float s1 = o1 * as_c, d1 = o1 * ad_c;
        #pragma unroll
        for (int ofs = 1; ofs < 16; ofs <<= 1) {
            s0 += __shfl_xor_sync(FULL, s0, ofs);
            d0 += __shfl_xor_sync(FULL, d0, ofs);
            s1 += __shfl_xor_sync(FULL, s1, ofs);
            d1 += __shfl_xor_sync(FULL, d1, ofs);
        }
        if (l16 == 0) {
            g_as1[(row0 + 2 * i) * 8 + head] = s0;
            g_ad1[(row0 + 2 * i) * 8 + head] = d0;
            g_as1[(row0 + 2 * i + 1) * 8 + head] = s1;
            g_ad1[(row0 + 2 * i + 1) * 8 + head] = d1;
        }
    }
}

// ---------------- GEMM2 + att2 fused ----------------
__global__ void __launch_bounds__(64) k_gemm2att2(const float* __restrict__ W,
                                                  const float* __restrict__ asv,
                                                  const float* __restrict__ adv) {
    __shared__ float shT[128][34];
    __shared__ float red[2][32][2];
    int c = threadIdx.x;  // 0..63
    int row0 = blockIdx.x * 32;
    int k0 = c, k1 = c + 64;
    #pragma unroll 4
    for (int r = 0; r < 32; r++) {
        shT[k0][r] = g_h[(row0 + r) * 128 + k0];
        shT[k1][r] = g_h[(row0 + r) * 128 + k1];
    }
    __syncthreads();

    unsigned long long acc[16];
    #pragma unroll
    for (int i = 0; i < 16; i++) acc[i] = 0ull;

    #pragma unroll 4
    for (int k = 0; k < 128; k++) {
        float w = W[k * 64 + c];
        unsigned long long w2 = pk2(w, w);
        const float2* col2 = (const float2*)&shT[k][0];
        #pragma unroll
        for (int i = 0; i < 16; i++) {
            float2 a = col2[i];
            acc[i] = fma2(pk2(a.x, a.y), w2, acc[i]);
        }
    }

    float as_c = asv[c], ad_c = adv[c];
    int lane = c & 31, wrp = c >> 5;
    #pragma unroll
    for (int i = 0; i < 16; i++) {
        float o0, o1;
        upk2(acc[i], o0, o1);
        g_xl2[(row0 + 2 * i) * 64 + c] = o0;
        g_xl2[(row0 + 2 * i + 1) * 64 + c] = o1;
        float s0 = o0 * as_c, d0 = o0 * ad_c;
        float s1 = o1 * as_c, d1 = o1 * ad_c;
        #pragma unroll
        for (int ofs = 1; ofs < 32; ofs <<= 1) {
            s0 += __shfl_xor_sync(FULL, s0, ofs);
            d0 += __shfl_xor_sync(FULL, d0, ofs);
            s1 += __shfl_xor_sync(FULL, s1, ofs);
            d1 += __shfl_xor_sync(FULL, d1, ofs);
        }
        if (lane == 0) {
            red[wrp][2 * i][0] = s0;
            red[wrp][2 * i][1] = d0;
            red[wrp][2 * i + 1][0] = s1;
            red[wrp][2 * i + 1][1] = d1;
        }
    }
    __syncthreads();
    if (c < 32) {
        g_as2[row0 + c] = red[0][c][0] + red[1][c][0];
        g_ad2[row0 + c] = red[0][c][1] + red[1][c][1];
    }
}

// ---------------- layer-1 aggregation: one warp per node, SINGLE PASS ----------------
__global__ void __launch_bounds__(256) k_agg1(const float* __restrict__ b1) {
    int gw = (blockIdx.x * blockDim.x + threadIdx.x) >> 5;
    if (gw >= N_NODES) return;
    int lane = threadIdx.x & 31;
    int dst = gw;
    int beg = g_off[dst], end = g_off[dst + 1];
    int h = lane & 7, g = lane >> 3;
    int col = lane << 2, hs = lane >> 2;

    float adst = g_ad1[dst * 8 + h];
    float wself = __expf(lrelu(g_as1[dst * 8 + h] + adst));
    // wself seeded once per 8-lane residue class (lanes 0..7) for the xor-8/16 tree
    float denom = (g == 0) ? wself : 0.f;
    float wself_sel = __shfl_sync(FULL, wself, hs);
    float4 xv = *(const float4*)&g_xl1[dst * 128 + col];
    float4 acc = make_float4(wself_sel * xv.x, wself_sel * xv.y,
                             wself_sel * xv.z, wself_sel * xv.w);

    for (int base = beg; base < end; base += 32) {
        int mycsr = (base + lane < end) ? g_csr[base + lane] : 0;
        int n = min(32, end - base);
        for (int sub = 0; sub < n; sub += 4) {
            int src_g = __shfl_sync(FULL, mycsr, sub + g);
            float e = lrelu(__ldg(&g_as1[src_g * 8 + h]) + adst);
            float w = ((sub + g) < n) ? __expf(e) : 0.f;
            denom += w;   // all 8 lanes of group g hold identical w; xor-8/16 tree never mixes within-group lanes
            #pragma unroll
            for (int j = 0; j < 4; j++) {
                if (sub + j < n) {   // warp-uniform condition
                    int srcj = __shfl_sync(FULL, mycsr, sub + j);
                    float wsel = __shfl_sync(FULL, w, (j << 3) + hs);
                    float4 v = *(const float4*)&g_xl1[srcj * 128 + col];
                    acc.x += wsel * v.x;
                    acc.y += wsel * v.y;
                    acc.z += wsel * v.z;
                    acc.w += wsel * v.w;
                }
            }
        }
    }
    denom += __shfl_xor_sync(FULL, denom, 8);
    denom += __shfl_xor_sync(FULL, denom, 16);
    float invS = 1.f / (denom + 1e-16f);
    float invS_sel = __shfl_sync(FULL, invS, hs);

    float4 o;
    o.x = elu_f(acc.x * invS_sel + b1[col + 0]);
    o.y = elu_f(acc.y * invS_sel + b1[col + 1]);
    o.z = elu_f(acc.z * invS_sel + b1[col + 2]);
    o.w = elu_f(acc.w * invS_sel + b1[col + 3]);
    *(float4*)&g_h[dst * 128 + col] = o;
}

// ---------------- layer-2 aggregation (H=1, C=64): split halves, SINGLE PASS ----------
// Halves of the warp accumulate disjoint 4-edge subgroups; shfls unconditional.
// Denominator: every lane accumulates its quad-group's w (identical within the
// quad); xor-4/8/16 butterfly crosses only quad boundaries, so each group is
// counted once. wself seeded once per bits-0..1 residue class (lanes 0..3).
__global__ void __launch_bounds__(256) k_agg2(const float* __restrict__ b2,
                                              float* __restrict__ out) {
    int gw = (blockIdx.x * blockDim.x + threadIdx.x) >> 5;
    if (gw >= N_NODES) return;
    int lane = threadIdx.x & 31;
    int q4 = lane >> 2;            // quad-group 0..7: computes weight for edge sub+q4
    int half = lane >> 4;          // 0 or 1: which 4-edge subgroup to accumulate
    int col = (lane & 15) << 2;    // feature cols
    int dst = gw;
    int beg = g_off[dst], end = g_off[dst + 1];

    float adst = g_ad2[dst];
    float wself = __expf(lrelu(g_as2[dst] + adst));
    float denom = (lane < 4) ? wself : 0.f;   // once per bits-0..1 residue class
    float4 acc = make_float4(0.f, 0.f, 0.f, 0.f);
    if (half == 0) {
        float4 xv = *(const float4*)&g_xl2[dst * 64 + col];
        acc = make_float4(wself * xv.x, wself * xv.y, wself * xv.z, wself * xv.w);
    }

    for (int base = beg; base < end; base += 32) {
        int mycsr = (base + lane < end) ? g_csr[base + lane] : 0;
        int n = min(32, end - base);
        for (int sub = 0; sub < n; sub += 8) {
            int eidx = sub + q4;
            int src_q = __shfl_sync(FULL, mycsr, eidx & 31);
            float e = lrelu(__ldg(&g_as2[src_q]) + adst);
            float w = (eidx < n) ? __expf(e) : 0.f;
            denom += w;   // identical within quad; butterfly won't double-count
            int jbase = sub + (half << 2);
            #pragma unroll
            for (int jj = 0; jj < 4; jj++) {
                int j = jbase + jj;
                // unconditional shfls — all 32 lanes participate every iteration
                int srcj = __shfl_sync(FULL, mycsr, j & 31);
                float wj = __shfl_sync(FULL, w, ((j - sub) & 7) << 2);
                if (j < n) {
                    float4 v = *(const float4*)&g_xl2[srcj * 64 + col];
                    acc.x += wj * v.x;
                    acc.y += wj * v.y;
                    acc.z += wj * v.z;
                    acc.w += wj * v.w;
                }
            }
        }
    }
    denom += __shfl_xor_sync(FULL, denom, 4);
    denom += __shfl_xor_sync(FULL, denom, 8);
    denom += __shfl_xor_sync(FULL, denom, 16);
    float invS = 1.f / (denom + 1e-16f);
    // combine halves (disjoint edge sets)
    acc.x += __shfl_xor_sync(FULL, acc.x, 16);
    acc.y += __shfl_xor_sync(FULL, acc.y, 16);
    acc.z += __shfl_xor_sync(FULL, acc.z, 16);
    acc.w += __shfl_xor_sync(FULL, acc.w, 16);

    if (lane < 16) {
        float4 o;
        o.x = acc.x * invS + b2[col + 0];
        o.y = acc.y * invS + b2[col + 1];
        o.z = acc.z * invS + b2[col + 2];
        o.w = acc.w * invS + b2[col + 3];
        *(float4*)&out[dst * 64 + col] = o;
    }
}

// ---------------- launch ----------------
extern "C" void kernel_launch(void* const* d_in, const int* in_sizes, int n_in,
                              void* d_out, int out_size) {
    const float* x   = (const float*)d_in[0];
    const int*   ei  = (const int*)d_in[1];
    const float* W1  = (const float*)d_in[2];
    const float* as1 = (const float*)d_in[3];
    const float* ad1 = (const float*)d_in[4];
    const float* b1  = (const float*)d_in[5];
    const float* W2  = (const float*)d_in[6];
    const float* as2 = (const float*)d_in[7];
    const float* ad2 = (const float*)d_in[8];
    const float* b2  = (const float*)d_in[9];
    float* out = (float*)d_out;
    int E = in_sizes[1] / 2;
    int n4t = (E >> 2) + 1;  // int4 threads + 1 tail thread

    k_zero<<<(N_NODES + 4 + 255) / 256, 256>>>();                 // 0
    k_hist<<<(n4t + 255) / 256, 256>>>(ei, E);                    // 1
    k_gemm1att1<<<N_NODES / 32, 128>>>(x, W1, as1, ad1);          // 2
    k_scan1<<<SCAN_B, 1024>>>();                                  // 3
    k_scan2<<<1, 32>>>();                                         // 4
    k_scan3<<<SCAN_B, 1024>>>();                                  // 5
    k_scatter<<<(n4t + 255) / 256, 256>>>(ei, E);                 // 6
    k_agg1<<<N_NODES / 8, 256>>>(b1);                             // 7
    k_gemm2att2<<<N_NODES / 32, 64>>>(W2, as2, ad2);              // 8
    k_agg2<<<N_NODES / 8, 256>>>(b2, out);                        // 9
}

// round 7
// speedup vs baseline: 1.2902x; 1.0094x over previous
#include <cuda_runtime.h>
#include <math.h>

#define N_NODES 100000
#define E_MAX   1600000
#define FULL    0xffffffffu
#define N4      (N_NODES / 4)        // 25000 int4 groups
#define SCAN_B  ((N4 + 1023) / 1024) // 25 scan blocks

// ---------------- scratch (static __device__ — no dynamic alloc) ----------------
__device__ int   g_deg[N_NODES + 4];
__device__ int   g_off[N_NODES + 4];
__device__ int   g_cur[N_NODES + 4];
__device__ int   g_csr[E_MAX];
__device__ int   g_blk[SCAN_B];

__device__ float g_xl1[N_NODES * 128];  // x @ W1
__device__ float g_as1[N_NODES * 8];    // a_src layer1
__device__ float g_ad1[N_NODES * 8];    // a_dst layer1
__device__ float g_h  [N_NODES * 128];  // elu(gat1 out)
__device__ float g_xl2[N_NODES * 64];   // h @ W2
__device__ float g_as2[N_NODES];
__device__ float g_ad2[N_NODES];

__device__ __forceinline__ float lrelu(float x) { return x > 0.f ? x : 0.2f * x; }
__device__ __forceinline__ float elu_f(float x) { return x > 0.f ? x : expm1f(x); }

// packed f32x2 helpers (FFMA2 — PTX-only, doubles fp32 FMA throughput on sm_103a)
__device__ __forceinline__ unsigned long long pk2(float lo, float hi) {
    unsigned long long r;
    asm("mov.b64 %0, {%1, %2};" : "=l"(r) : "f"(lo), "f"(hi));
    return r;
}
__device__ __forceinline__ void upk2(unsigned long long v, float& lo, float& hi) {
    asm("mov.b64 {%0, %1}, %2;" : "=f"(lo), "=f"(hi) : "l"(v));
}
__device__ __forceinline__ unsigned long long fma2(unsigned long long a,
                                                   unsigned long long b,
                                                   unsigned long long c) {
    unsigned long long d;
    asm("fma.rn.f32x2 %0, %1, %2, %3;" : "=l"(d) : "l"(a), "l"(b), "l"(c));
    return d;
}

// ---------------- CSR build ----------------
__global__ void k_zero() {
    int i = blockIdx.x * blockDim.x + threadIdx.x;
    if (i < N_NODES + 4) g_deg[i] = 0;
}

__global__ void k_hist(const int* __restrict__ ei, int E) {
    int t = blockIdx.x * blockDim.x + threadIdx.x;
    int n4 = E >> 2;
    const int4* d4 = (const int4*)(ei + E);
    if (t < n4) {
        int4 v = d4[t];
        atomicAdd(&g_deg[v.x], 1);
        atomicAdd(&g_deg[v.y], 1);
        atomicAdd(&g_deg[v.z], 1);
        atomicAdd(&g_deg[v.w], 1);
    } else if (t == n4) {
        for (int e = n4 * 4; e < E; e++) atomicAdd(&g_deg[ei[E + e]], 1);
    }
}

// ---- multi-block scan: phase 1 — per-block exclusive scan + block totals ----
__global__ void __launch_bounds__(1024) k_scan1() {
    __shared__ int warp_sums[32];
    int tid = threadIdx.x, lane = tid & 31, wid = tid >> 5;
    int i = blockIdx.x * 1024 + tid;
    const int4* deg4 = (const int4*)g_deg;
    int4* off4 = (int4*)g_off;

    int4 v = (i < N4) ? deg4[i] : make_int4(0, 0, 0, 0);
    int tot = v.x + v.y + v.z + v.w;
    int xs = tot;
    #pragma unroll
    for (int o = 1; o < 32; o <<= 1) {
        int t = __shfl_up_sync(FULL, xs, o);
        if (lane >= o) xs += t;
    }
    if (lane == 31) warp_sums[wid] = xs;
    __syncthreads();
    if (wid == 0) {
        int ws = warp_sums[lane];
        #pragma unroll
        for (int o = 1; o < 32; o <<= 1) {
            int t = __shfl_up_sync(FULL, ws, o);
            if (lane >= o) ws += t;
        }
        warp_sums[lane] = ws;
    }
    __syncthreads();
    int incl = xs + (wid > 0 ? warp_sums[wid - 1] : 0);
    int b0 = incl - tot;
    if (i < N4) {
        int4 o;
        o.x = b0;
        o.y = b0 + v.x;
        o.z = o.y + v.y;
        o.w = o.z + v.z;
        off4[i] = o;
    }
    if (tid == 0) g_blk[blockIdx.x] = warp_sums[31];
}

// ---- scan phase 2+3 merged: every block warp-scans the 25 block totals, then
// adds its block offset and fills g_cur ----
__global__ void __launch_bounds__(1024) k_scan3() {
    __shared__ int s_off[32];
    int tid = threadIdx.x;
    if (tid < 32) {
        int t = (tid < SCAN_B) ? g_blk[tid] : 0;
        int xs = t;
        #pragma unroll
        for (int o = 1; o < 32; o <<= 1) {
            int u = __shfl_up_sync(FULL, xs, o);
            if (tid >= o) xs += u;
        }
        s_off[tid] = xs - t;
        if (blockIdx.x == 0 && tid == 31) g_off[N_NODES] = xs;
    }
    __syncthreads();
    int i = blockIdx.x * 1024 + tid;
    if (i < N4) {
        int add = s_off[blockIdx.x];
        int4* off4 = (int4*)g_off;
        int4* cur4 = (int4*)g_cur;
        int4 o = off4[i];
        o.x += add; o.y += add; o.z += add; o.w += add;
        off4[i] = o;
        cur4[i] = o;
    }
}

__global__ void k_scatter(const int* __restrict__ ei, int E) {
    int t = blockIdx.x * blockDim.x + threadIdx.x;
    int n4 = E >> 2;
    const int4* s4 = (const int4*)ei;
    const int4* d4 = (const int4*)(ei + E);
    if (t < n4) {
        int4 s = s4[t];
        int4 d = d4[t];
        g_csr[atomicAdd(&g_cur[d.x], 1)] = s.x;
        g_csr[atomicAdd(&g_cur[d.y], 1)] = s.y;
        g_csr[atomicAdd(&g_cur[d.z], 1)] = s.z;
        g_csr[atomicAdd(&g_cur[d.w], 1)] = s.w;
    } else if (t == n4) {
        for (int e = n4 * 4; e < E; e++)
            g_csr[atomicAdd(&g_cur[ei[E + e]], 1)] = ei[e];
    }
}

// ---------------- GEMM1 + att1 fused ----------------
// 32 rows/block, 128 threads (1 out-col each). Shared row stride 36 floats
// (144 B, 16B-aligned) enables LDS.128 broadcast reads: 8 LDS.128 + 16 FFMA2 / k.
__global__ void __launch_bounds__(128) k_gemm1att1(const float* __restrict__ x,
                                                   const float* __restrict__ W,
                                                   const float* __restrict__ asv,
                                                   const float* __restrict__ adv) {
    __shared__ __align__(16) float sxT[128][36];
    int c = threadIdx.x;
    int row0 = blockIdx.x * 32;
    #pragma unroll 8
    for (int r = 0; r < 32; r++)
        sxT[c][r] = x[(row0 + r) * 128 + c];
    __syncthreads();

    unsigned long long acc[16];
    #pragma unroll
    for (int i = 0; i < 16; i++) acc[i] = 0ull;

    #pragma unroll 4
    for (int k = 0; k < 128; k++) {
        float w = W[k * 128 + c];
        unsigned long long w2 = pk2(w, w);
        const float4* col4 = (const float4*)&sxT[k][0];
        #pragma unroll
        for (int i = 0; i < 8; i++) {
            float4 a = col4[i];
            acc[2 * i]     = fma2(pk2(a.x, a.y), w2, acc[2 * i]);
            acc[2 * i + 1] = fma2(pk2(a.z, a.w), w2, acc[2 * i + 1]);
        }
    }

    float as_c = asv[c], ad_c = adv[c];
    int head = c >> 4, l16 = c & 15;
    #pragma unroll
    for (int i = 0; i < 16; i++) {
        float o0, o1;
        upk2(acc[i], o0, o1);
        g_xl1[(row0 + 2 * i) * 128 + c] = o0;
        g_xl1[(row0 + 2 * i + 1) * 128 + c] = o1;
        float s0 = o0 * as_c, d0 = o0 * ad_c;
        float s1 = o1 * as_c, d1 = o1 * ad_c;
        #pragma unroll
        for (int ofs = 1; ofs < 16; ofs <<= 1) {
            s0 += __shfl_xor_sync(FULL, s0, ofs);
            d0 += __shfl_xor_sync(FULL, d0, ofs);
            s1 += __shfl_xor_sync(FULL, s1, ofs);
            d1 += __shfl_xor_sync(FULL, d1, ofs);
        }
        if (l16 == 0) {
            g_as1[(row0 + 2 * i) * 8 + head] = s0;
            g_ad1[(row0 + 2 * i) * 8 + head] = d0;
            g_as1[(row0 + 2 * i + 1) * 8 + head] = s1;
            g_ad1[(row0 + 2 * i + 1) * 8 + head] = d1;
        }
    }
}

// ---------------- GEMM2 + att2 fused ----------------
__global__ void __launch_bounds__(64) k_gemm2att2(const float* __restrict__ W,
                                                  const float* __restrict__ asv,
                                                  const float* __restrict__ adv) {
    __shared__ __align__(16) float shT[128][36];
    __shared__ float red[2][32][2];
    int c = threadIdx.x;  // 0..63
    int row0 = blockIdx.x * 32;
    int k0 = c, k1 = c + 64;
    #pragma unroll 4
    for (int r = 0; r < 32; r++) {
        shT[k0][r] = g_h[(row0 + r) * 128 + k0];
        shT[k1][r] = g_h[(row0 + r) * 128 + k1];
    }
    __syncthreads();

    unsigned long long acc[16];
    #pragma unroll
    for (int i = 0; i < 16; i++) acc[i] = 0ull;

    #pragma unroll 4
    for (int k = 0; k < 128; k++) {
        float w = W[k * 64 + c];
        unsigned long long w2 = pk2(w, w);
        const float4* col4 = (const float4*)&shT[k][0];
        #pragma unroll
        for (int i = 0; i < 8; i++) {
            float4 a = col4[i];
            acc[2 * i]     = fma2(pk2(a.x, a.y), w2, acc[2 * i]);
            acc[2 * i + 1] = fma2(pk2(a.z, a.w), w2, acc[2 * i + 1]);
        }
    }

    float as_c = asv[c], ad_c = adv[c];
    int lane = c & 31, wrp = c >> 5;
    #pragma unroll
    for (int i = 0; i < 16; i++) {
        float o0, o1;
        upk2(acc[i], o0, o1);
        g_xl2[(row0 + 2 * i) * 64 + c] = o0;
        g_xl2[(row0 + 2 * i + 1) * 64 + c] = o1;
        float s0 = o0 * as_c, d0 = o0 * ad_c;
        float s1 = o1 * as_c, d1 = o1 * ad_c;
        #pragma unroll
        for (int ofs = 1; ofs < 32; ofs <<= 1) {
            s0 += __shfl_xor_sync(FULL, s0, ofs);
            d0 += __shfl_xor_sync(FULL, d0, ofs);
            s1 += __shfl_xor_sync(FULL, s1, ofs);
            d1 += __shfl_xor_sync(FULL, d1, ofs);
        }
        if (lane == 0) {
            red[wrp][2 * i][0] = s0;
            red[wrp][2 * i][1] = d0;
            red[wrp][2 * i + 1][0] = s1;
            red[wrp][2 * i + 1][1] = d1;
        }
    }
    __syncthreads();
    if (c < 32) {
        g_as2[row0 + c] = red[0][c][0] + red[1][c][0];
        g_ad2[row0 + c] = red[0][c][1] + red[1][c][1];
    }
}

// ---------------- layer-1 aggregation: one warp per node, SINGLE PASS ----------------
__global__ void __launch_bounds__(256) k_agg1(const float* __restrict__ b1) {
    int gw = (blockIdx.x * blockDim.x + threadIdx.x) >> 5;
    if (gw >= N_NODES) return;
    int lane = threadIdx.x & 31;
    int dst = gw;
    int beg = g_off[dst], end = g_off[dst + 1];
    int h = lane & 7, g = lane >> 3;
    int col = lane << 2, hs = lane >> 2;

    float adst = g_ad1[dst * 8 + h];
    float wself = __expf(lrelu(g_as1[dst * 8 + h] + adst));
    float denom = (g == 0) ? wself : 0.f;   // once per 8-lane residue class
    float wself_sel = __shfl_sync(FULL, wself, hs);
    float4 xv = *(const float4*)&g_xl1[dst * 128 + col];
    unsigned long long ws2 = pk2(wself_sel, wself_sel);
    unsigned long long a01 = fma2(pk2(xv.x, xv.y), ws2, 0ull);
    unsigned long long a23 = fma2(pk2(xv.z, xv.w), ws2, 0ull);

    for (int base = beg; base < end; base += 32) {
        int mycsr = (base + lane < end) ? g_csr[base + lane] : 0;
        int n = min(32, end - base);
        for (int sub = 0; sub < n; sub += 4) {
            int src_g = __shfl_sync(FULL, mycsr, sub + g);
            float e = lrelu(__ldg(&g_as1[src_g * 8 + h]) + adst);
            float w = ((sub + g) < n) ? __expf(e) : 0.f;
            denom += w;   // identical within 8-lane group; xor-8/16 tree counts once
            #pragma unroll
            for (int j = 0; j < 4; j++) {
                if (sub + j < n) {   // warp-uniform condition
                    int srcj = __shfl_sync(FULL, mycsr, sub + j);
                    float wsel = __shfl_sync(FULL, w, (j << 3) + hs);
                    float4 v = *(const float4*)&g_xl1[srcj * 128 + col];
                    unsigned long long w2 = pk2(wsel, wsel);
                    a01 = fma2(pk2(v.x, v.y), w2, a01);
                    a23 = fma2(pk2(v.z, v.w), w2, a23);
                }
            }
        }
    }
    denom += __shfl_xor_sync(FULL, denom, 8);
    denom += __shfl_xor_sync(FULL, denom, 16);
    float invS = 1.f / (denom + 1e-16f);
    float invS_sel = __shfl_sync(FULL, invS, hs);

    float ax, ay, az, aw;
    upk2(a01, ax, ay);
    upk2(a23, az, aw);
    float4 o;
    o.x = elu_f(ax * invS_sel + b1[col + 0]);
    o.y = elu_f(ay * invS_sel + b1[col + 1]);
    o.z = elu_f(az * invS_sel + b1[col + 2]);
    o.w = elu_f(aw * invS_sel + b1[col + 3]);
    *(float4*)&g_h[dst * 128 + col] = o;
}

// ---------------- layer-2 aggregation (H=1, C=64): split halves, SINGLE PASS ----------
__global__ void __launch_bounds__(256) k_agg2(const float* __restrict__ b2,
                                              float* __restrict__ out) {
    int gw = (blockIdx.x * blockDim.x + threadIdx.x) >> 5;
    if (gw >= N_NODES) return;
    int lane = threadIdx.x & 31;
    int q4 = lane >> 2;            // quad-group 0..7: weight for edge sub+q4
    int half = lane >> 4;          // 0/1: which 4-edge subgroup to accumulate
    int col = (lane & 15) << 2;    // feature cols
    int dst = gw;
    int beg = g_off[dst], end = g_off[dst + 1];

    float adst = g_ad2[dst];
    float wself = __expf(lrelu(g_as2[dst] + adst));
    float denom = (lane < 4) ? wself : 0.f;   // once per bits-0..1 residue class
    unsigned long long a01 = 0ull, a23 = 0ull;
    if (half == 0) {
        float4 xv = *(const float4*)&g_xl2[dst * 64 + col];
        unsigned long long ws2 = pk2(wself, wself);
        a01 = fma2(pk2(xv.x, xv.y), ws2, 0ull);
        a23 = fma2(pk2(xv.z, xv.w), ws2, 0ull);
    }

    for (int base = beg; base < end; base += 32) {
        int mycsr = (base + lane < end) ? g_csr[base + lane] : 0;
        int n = min(32, end - base);
        for (int sub = 0; sub < n; sub += 8) {
            int eidx = sub + q4;
            int src_q = __shfl_sync(FULL, mycsr, eidx & 31);
            float e = lrelu(__ldg(&g_as2[src_q]) + adst);
            float w = (eidx < n) ? __expf(e) : 0.f;
            denom += w;   // identical within quad; xor-4/8/16 counts once
            int jbase = sub + (half << 2);
            #pragma unroll
            for (int jj = 0; jj < 4; jj++) {
                int j = jbase + jj;
                // unconditional shfls — all 32 lanes participate
                int srcj = __shfl_sync(FULL, mycsr, j & 31);
                float wj = __shfl_sync(FULL, w, ((j - sub) & 7) << 2);
                if (j < n) {
                    float4 v = *(const float4*)&g_xl2[srcj * 64 + col];
                    unsigned long long w2 = pk2(wj, wj);
                    a01 = fma2(pk2(v.x, v.y), w2, a01);
                    a23 = fma2(pk2(v.z, v.w), w2, a23);
                }
            }
        }
    }
    denom += __shfl_xor_sync(FULL, denom, 4);
    denom += __shfl_xor_sync(FULL, denom, 8);
    denom += __shfl_xor_sync(FULL, denom, 16);
    float invS = 1.f / (denom + 1e-16f);
    // combine halves (disjoint edge sets) — packed adds via shfl on 32-bit halves
    float ax, ay, az, aw;
    upk2(a01, ax, ay);
    upk2(a23, az, aw);
    ax += __shfl_xor_sync(FULL, ax, 16);
    ay += __shfl_xor_sync(FULL, ay, 16);
    az += __shfl_xor_sync(FULL, az, 16);
    aw += __shfl_xor_sync(FULL, aw, 16);

    if (lane < 16) {
        float4 o;
        o.x = ax * invS + b2[col + 0];
        o.y = ay * invS + b2[col + 1];
        o.z = az * invS + b2[col + 2];
        o.w = aw * invS + b2[col + 3];
        *(float4*)&out[dst * 64 + col] = o;
    }
}

// ---------------- launch ----------------
extern "C" void kernel_launch(void* const* d_in, const int* in_sizes, int n_in,
                              void* d_out, int out_size) {
    const float* x   = (const float*)d_in[0];
    const int*   ei  = (const int*)d_in[1];
    const float* W1  = (const float*)d_in[2];
    const float* as1 = (const float*)d_in[3];
    const float* ad1 = (const float*)d_in[4];
    const float* b1  = (const float*)d_in[5];
    const float* W2  = (const float*)d_in[6];
    const float* as2 = (const float*)d_in[7];
    const float* ad2 = (const float*)d_in[8];
    const float* b2  = (const float*)d_in[9];
    float* out = (float*)d_out;
    int E = in_sizes[1] / 2;
    int n4t = (E >> 2) + 1;  // int4 threads + 1 tail thread

    k_zero<<<(N_NODES + 4 + 255) / 256, 256>>>();                 // 0
    k_hist<<<(n4t + 255) / 256, 256>>>(ei, E);                    // 1
    k_gemm1att1<<<N_NODES / 32, 128>>>(x, W1, as1, ad1);          // 2
    k_scan1<<<SCAN_B, 1024>>>();                                  // 3
    k_scan3<<<SCAN_B, 1024>>>();                                  // 4
    k_scatter<<<(n4t + 255) / 256, 256>>>(ei, E);                 // 5
    k_agg1<<<N_NODES / 8, 256>>>(b1);                             // 6
    k_gemm2att2<<<N_NODES / 32, 64>>>(W2, as2, ad2);              // 7
    k_agg2<<<N_NODES / 8, 256>>>(b2, out);                        // 8
}

// round 8
// speedup vs baseline: 1.3505x; 1.0468x over previous
#include <cuda_runtime.h>
#include <math.h>

#define N_NODES 100000
#define E_MAX   1600000
#define FULL    0xffffffffu
#define N4      (N_NODES / 4)        // 25000 int4 groups
#define SCAN_B  ((N4 + 1023) / 1024) // 25 scan blocks

// ---------------- scratch (static __device__ — no dynamic alloc) ----------------
__device__ int   g_deg[N_NODES + 4];
__device__ int   g_off[N_NODES + 4];
__device__ int   g_cur[N_NODES + 4];
__device__ int   g_csr[E_MAX];
__device__ int   g_blk[SCAN_B];

__device__ float g_xl1[N_NODES * 128];  // x @ W1
__device__ float g_as1[N_NODES * 8];    // a_src layer1
__device__ float g_ad1[N_NODES * 8];    // a_dst layer1
__device__ float g_h  [N_NODES * 128];  // elu(gat1 out)
__device__ float g_xl2[N_NODES * 64];   // h @ W2
__device__ float g_as2[N_NODES];
__device__ float g_ad2[N_NODES];

__device__ __forceinline__ float lrelu(float x) { return x > 0.f ? x : 0.2f * x; }
__device__ __forceinline__ float elu_f(float x) { return x > 0.f ? x : expm1f(x); }

// packed f32x2 helpers (FFMA2 — PTX-only, doubles fp32 FMA throughput on sm_103a)
__device__ __forceinline__ unsigned long long pk2(float lo, float hi) {
    unsigned long long r;
    asm("mov.b64 %0, {%1, %2};" : "=l"(r) : "f"(lo), "f"(hi));
    return r;
}
__device__ __forceinline__ void upk2(unsigned long long v, float& lo, float& hi) {
    asm("mov.b64 {%0, %1}, %2;" : "=f"(lo), "=f"(hi) : "l"(v));
}
__device__ __forceinline__ unsigned long long fma2(unsigned long long a,
                                                   unsigned long long b,
                                                   unsigned long long c) {
    unsigned long long d;
    asm("fma.rn.f32x2 %0, %1, %2, %3;" : "=l"(d) : "l"(a), "l"(b), "l"(c));
    return d;
}

// ---------------- CSR build ----------------
__global__ void k_zero() {
    int i = blockIdx.x * blockDim.x + threadIdx.x;
    if (i < N_NODES + 4) g_deg[i] = 0;
}

__global__ void k_hist(const int* __restrict__ ei, int E) {
    int t = blockIdx.x * blockDim.x + threadIdx.x;
    int n4 = E >> 2;
    const int4* d4 = (const int4*)(ei + E);
    if (t < n4) {
        int4 v = d4[t];
        atomicAdd(&g_deg[v.x], 1);
        atomicAdd(&g_deg[v.y], 1);
        atomicAdd(&g_deg[v.z], 1);
        atomicAdd(&g_deg[v.w], 1);
    } else if (t == n4) {
        for (int e = n4 * 4; e < E; e++) atomicAdd(&g_deg[ei[E + e]], 1);
    }
}

// ---- multi-block scan: phase 1 — per-block exclusive scan + block totals ----
__global__ void __launch_bounds__(1024) k_scan1() {
    __shared__ int warp_sums[32];
    int tid = threadIdx.x, lane = tid & 31, wid = tid >> 5;
    int i = blockIdx.x * 1024 + tid;
    const int4* deg4 = (const int4*)g_deg;
    int4* off4 = (int4*)g_off;

    int4 v = (i < N4) ? deg4[i] : make_int4(0, 0, 0, 0);
    int tot = v.x + v.y + v.z + v.w;
    int xs = tot;
    #pragma unroll
    for (int o = 1; o < 32; o <<= 1) {
        int t = __shfl_up_sync(FULL, xs, o);
        if (lane >= o) xs += t;
    }
    if (lane == 31) warp_sums[wid] = xs;
    __syncthreads();
    if (wid == 0) {
        int ws = warp_sums[lane];
        #pragma unroll
        for (int o = 1; o < 32; o <<= 1) {
            int t = __shfl_up_sync(FULL, ws, o);
            if (lane >= o) ws += t;
        }
        warp_sums[lane] = ws;
    }
    __syncthreads();
    int incl = xs + (wid > 0 ? warp_sums[wid - 1] : 0);
    int b0 = incl - tot;
    if (i < N4) {
        int4 o;
        o.x = b0;
        o.y = b0 + v.x;
        o.z = o.y + v.y;
        o.w = o.z + v.z;
        off4[i] = o;
    }
    if (tid == 0) g_blk[blockIdx.x] = warp_sums[31];
}

// ---- scan phase 2+3 merged: every block warp-scans the 25 block totals, then
// adds its block offset and fills g_cur ----
__global__ void __launch_bounds__(1024) k_scan3() {
    __shared__ int s_off[32];
    int tid = threadIdx.x;
    if (tid < 32) {
        int t = (tid < SCAN_B) ? g_blk[tid] : 0;
        int xs = t;
        #pragma unroll
        for (int o = 1; o < 32; o <<= 1) {
            int u = __shfl_up_sync(FULL, xs, o);
            if (tid >= o) xs += u;
        }
        s_off[tid] = xs - t;
        if (blockIdx.x == 0 && tid == 31) g_off[N_NODES] = xs;
    }
    __syncthreads();
    int i = blockIdx.x * 1024 + tid;
    if (i < N4) {
        int add = s_off[blockIdx.x];
        int4* off4 = (int4*)g_off;
        int4* cur4 = (int4*)g_cur;
        int4 o = off4[i];
        o.x += add; o.y += add; o.z += add; o.w += add;
        off4[i] = o;
        cur4[i] = o;
    }
}

__global__ void k_scatter(const int* __restrict__ ei, int E) {
    int t = blockIdx.x * blockDim.x + threadIdx.x;
    int n4 = E >> 2;
    const int4* s4 = (const int4*)ei;
    const int4* d4 = (const int4*)(ei + E);
    if (t < n4) {
        int4 s = s4[t];
        int4 d = d4[t];
        g_csr[atomicAdd(&g_cur[d.x], 1)] = s.x;
        g_csr[atomicAdd(&g_cur[d.y], 1)] = s.y;
        g_csr[atomicAdd(&g_cur[d.z], 1)] = s.z;
        g_csr[atomicAdd(&g_cur[d.w], 1)] = s.w;
    } else if (t == n4) {
        for (int e = n4 * 4; e < E; e++)
            g_csr[atomicAdd(&g_cur[ei[E + e]], 1)] = ei[e];
    }
}

// ---------------- GEMM1 + att1 fused ----------------
__global__ void __launch_bounds__(128) k_gemm1att1(const float* __restrict__ x,
                                                   const float* __restrict__ W,
                                                   const float* __restrict__ asv,
                                                   const float* __restrict__ adv) {
    __shared__ __align__(16) float sxT[128][36];
    int c = threadIdx.x;
    int row0 = blockIdx.x * 32;
    #pragma unroll 8
    for (int r = 0; r < 32; r++)
        sxT[c][r] = x[(row0 + r) * 128 + c];
    __syncthreads();

    unsigned long long acc[16];
    #pragma unroll
    for (int i = 0; i < 16; i++) acc[i] = 0ull;

    #pragma unroll 4
    for (int k = 0; k < 128; k++) {
        float w = W[k * 128 + c];
        unsigned long long w2 = pk2(w, w);
        const float4* col4 = (const float4*)&sxT[k][0];
        #pragma unroll
        for (int i = 0; i < 8; i++) {
            float4 a = col4[i];
            acc[2 * i]     = fma2(pk2(a.x, a.y), w2, acc[2 * i]);
            acc[2 * i + 1] = fma2(pk2(a.z, a.w), w2, acc[2 * i + 1]);
        }
    }

    float as_c = asv[c], ad_c = adv[c];
    int head = c >> 4, l16 = c & 15;
    #pragma unroll
    for (int i = 0; i < 16; i++) {
        float o0, o1;
        upk2(acc[i], o0, o1);
        g_xl1[(row0 + 2 * i) * 128 + c] = o0;
        g_xl1[(row0 + 2 * i + 1) * 128 + c] = o1;
        float s0 = o0 * as_c, d0 = o0 * ad_c;
        float s1 = o1 * as_c, d1 = o1 * ad_c;
        #pragma unroll
        for (int ofs = 1; ofs < 16; ofs <<= 1) {
            s0 += __shfl_xor_sync(FULL, s0, ofs);
            d0 += __shfl_xor_sync(FULL, d0, ofs);
            s1 += __shfl_xor_sync(FULL, s1, ofs);
            d1 += __shfl_xor_sync(FULL, d1, ofs);
        }
        if (l16 == 0) {
            g_as1[(row0 + 2 * i) * 8 + head] = s0;
            g_ad1[(row0 + 2 * i) * 8 + head] = d0;
            g_as1[(row0 + 2 * i + 1) * 8 + head] = s1;
            g_ad1[(row0 + 2 * i + 1) * 8 + head] = d1;
        }
    }
}

// ---------------- GEMM2 + att2 fused ----------------
__global__ void __launch_bounds__(64) k_gemm2att2(const float* __restrict__ W,
                                                  const float* __restrict__ asv,
                                                  const float* __restrict__ adv) {
    __shared__ __align__(16) float shT[128][36];
    __shared__ float red[2][32][2];
    int c = threadIdx.x;  // 0..63
    int row0 = blockIdx.x * 32;
    int k0 = c, k1 = c + 64;
    #pragma unroll 4
    for (int r = 0; r < 32; r++) {
        shT[k0][r] = g_h[(row0 + r) * 128 + k0];
        shT[k1][r] = g_h[(row0 + r) * 128 + k1];
    }
    __syncthreads();

    unsigned long long acc[16];
    #pragma unroll
    for (int i = 0; i < 16; i++) acc[i] = 0ull;

    #pragma unroll 4
    for (int k = 0; k < 128; k++) {
        float w = W[k * 64 + c];
        unsigned long long w2 = pk2(w, w);
        const float4* col4 = (const float4*)&shT[k][0];
        #pragma unroll
        for (int i = 0; i < 8; i++) {
            float4 a = col4[i];
            acc[2 * i]     = fma2(pk2(a.x, a.y), w2, acc[2 * i]);
            acc[2 * i + 1] = fma2(pk2(a.z, a.w), w2, acc[2 * i + 1]);
        }
    }

    float as_c = asv[c], ad_c = adv[c];
    int lane = c & 31, wrp = c >> 5;
    #pragma unroll
    for (int i = 0; i < 16; i++) {
        float o0, o1;
        upk2(acc[i], o0, o1);
        g_xl2[(row0 + 2 * i) * 64 + c] = o0;
        g_xl2[(row0 + 2 * i + 1) * 64 + c] = o1;
        float s0 = o0 * as_c, d0 = o0 * ad_c;
        float s1 = o1 * as_c, d1 = o1 * ad_c;
        #pragma unroll
        for (int ofs = 1; ofs < 32; ofs <<= 1) {
            s0 += __shfl_xor_sync(FULL, s0, ofs);
            d0 += __shfl_xor_sync(FULL, d0, ofs);
            s1 += __shfl_xor_sync(FULL, s1, ofs);
            d1 += __shfl_xor_sync(FULL, d1, ofs);
        }
        if (lane == 0) {
            red[wrp][2 * i][0] = s0;
            red[wrp][2 * i][1] = d0;
            red[wrp][2 * i + 1][0] = s1;
            red[wrp][2 * i + 1][1] = d1;
        }
    }
    __syncthreads();
    if (c < 32) {
        g_as2[row0 + c] = red[0][c][0] + red[1][c][0];
        g_ad2[row0 + c] = red[0][c][1] + red[1][c][1];
    }
}

// ---------------- layer-1 aggregation: one warp per node, SINGLE PASS ----------------
__global__ void __launch_bounds__(256) k_agg1(const float* __restrict__ b1) {
    int gw = (blockIdx.x * blockDim.x + threadIdx.x) >> 5;
    if (gw >= N_NODES) return;
    int lane = threadIdx.x & 31;
    int dst = gw;
    int beg = g_off[dst], end = g_off[dst + 1];
    int h = lane & 7, g = lane >> 3;
    int col = lane << 2, hs = lane >> 2;

    float adst = g_ad1[dst * 8 + h];
    float wself = __expf(lrelu(g_as1[dst * 8 + h] + adst));
    float denom = (g == 0) ? wself : 0.f;   // once per 8-lane residue class
    float wself_sel = __shfl_sync(FULL, wself, hs);
    float4 xv = *(const float4*)&g_xl1[dst * 128 + col];
    unsigned long long ws2 = pk2(wself_sel, wself_sel);
    unsigned long long a01 = fma2(pk2(xv.x, xv.y), ws2, 0ull);
    unsigned long long a23 = fma2(pk2(xv.z, xv.w), ws2, 0ull);

    for (int base = beg; base < end; base += 32) {
        int mycsr = (base + lane < end) ? g_csr[base + lane] : 0;
        int n = min(32, end - base);
        for (int sub = 0; sub < n; sub += 4) {
            int src_g = __shfl_sync(FULL, mycsr, sub + g);
            float e = lrelu(__ldg(&g_as1[src_g * 8 + h]) + adst);
            float w = ((sub + g) < n) ? __expf(e) : 0.f;
            denom += w;   // identical within 8-lane group; xor-8/16 tree counts once
            #pragma unroll
            for (int j = 0; j < 4; j++) {
                if (sub + j < n) {   // warp-uniform condition
                    int srcj = __shfl_sync(FULL, mycsr, sub + j);
                    float wsel = __shfl_sync(FULL, w, (j << 3) + hs);
                    float4 v = *(const float4*)&g_xl1[srcj * 128 + col];
                    unsigned long long w2 = pk2(wsel, wsel);
                    a01 = fma2(pk2(v.x, v.y), w2, a01);
                    a23 = fma2(pk2(v.z, v.w), w2, a23);
                }
            }
        }
    }
    denom += __shfl_xor_sync(FULL, denom, 8);
    denom += __shfl_xor_sync(FULL, denom, 16);
    float invS = 1.f / (denom + 1e-16f);
    float invS_sel = __shfl_sync(FULL, invS, hs);

    float ax, ay, az, aw;
    upk2(a01, ax, ay);
    upk2(a23, az, aw);
    float4 o;
    o.x = elu_f(ax * invS_sel + b1[col + 0]);
    o.y = elu_f(ay * invS_sel + b1[col + 1]);
    o.z = elu_f(az * invS_sel + b1[col + 2]);
    o.w = elu_f(aw * invS_sel + b1[col + 3]);
    *(float4*)&g_h[dst * 128 + col] = o;
}

// ---------------- layer-2 aggregation (H=1, C=64): split halves, SINGLE PASS ----------
__global__ void __launch_bounds__(256) k_agg2(const float* __restrict__ b2,
                                              float* __restrict__ out) {
    int gw = (blockIdx.x * blockDim.x + threadIdx.x) >> 5;
    if (gw >= N_NODES) return;
    int lane = threadIdx.x & 31;
    int q4 = lane >> 2;            // quad-group 0..7: weight for edge sub+q4
    int half = lane >> 4;          // 0/1: which 4-edge subgroup to accumulate
    int col = (lane & 15) << 2;    // feature cols
    int dst = gw;
    int beg = g_off[dst], end = g_off[dst + 1];

    float adst = g_ad2[dst];
    float wself = __expf(lrelu(g_as2[dst] + adst));
    float denom = (lane < 4) ? wself : 0.f;   // once per bits-0..1 residue class
    unsigned long long a01 = 0ull, a23 = 0ull;
    if (half == 0) {
        float4 xv = *(const float4*)&g_xl2[dst * 64 + col];
        unsigned long long ws2 = pk2(wself, wself);
        a01 = fma2(pk2(xv.x, xv.y), ws2, 0ull);
        a23 = fma2(pk2(xv.z, xv.w), ws2, 0ull);
    }

    for (int base = beg; base < end; base += 32) {
        int mycsr = (base + lane < end) ? g_csr[base + lane] : 0;
        int n = min(32, end - base);
        for (int sub = 0; sub < n; sub += 8) {
            int eidx = sub + q4;
            int src_q = __shfl_sync(FULL, mycsr, eidx & 31);
            float e = lrelu(__ldg(&g_as2[src_q]) + adst);
            float w = (eidx < n) ? __expf(e) : 0.f;
            denom += w;   // identical within quad; xor-4/8/16 counts once
            int jbase = sub + (half << 2);
            #pragma unroll
            for (int jj = 0; jj < 4; jj++) {
                int j = jbase + jj;
                // unconditional shfls — all 32 lanes participate
                int srcj = __shfl_sync(FULL, mycsr, j & 31);
                float wj = __shfl_sync(FULL, w, ((j - sub) & 7) << 2);
                if (j < n) {
                    float4 v = *(const float4*)&g_xl2[srcj * 64 + col];
                    unsigned long long w2 = pk2(wj, wj);
                    a01 = fma2(pk2(v.x, v.y), w2, a01);
                    a23 = fma2(pk2(v.z, v.w), w2, a23);
                }
            }
        }
    }
    denom += __shfl_xor_sync(FULL, denom, 4);
    denom += __shfl_xor_sync(FULL, denom, 8);
    denom += __shfl_xor_sync(FULL, denom, 16);
    float invS = 1.f / (denom + 1e-16f);
    float ax, ay, az, aw;
    upk2(a01, ax, ay);
    upk2(a23, az, aw);
    ax += __shfl_xor_sync(FULL, ax, 16);
    ay += __shfl_xor_sync(FULL, ay, 16);
    az += __shfl_xor_sync(FULL, az, 16);
    aw += __shfl_xor_sync(FULL, aw, 16);

    if (lane < 16) {
        float4 o;
        o.x = ax * invS + b2[col + 0];
        o.y = ay * invS + b2[col + 1];
        o.z = az * invS + b2[col + 2];
        o.w = aw * invS + b2[col + 3];
        *(float4*)&out[dst * 64 + col] = o;
    }
}

// ---------------- launch: fork-join overlap of CSR build with GEMM1 ----------------
extern "C" void kernel_launch(void* const* d_in, const int* in_sizes, int n_in,
                              void* d_out, int out_size) {
    const float* x   = (const float*)d_in[0];
    const int*   ei  = (const int*)d_in[1];
    const float* W1  = (const float*)d_in[2];
    const float* as1 = (const float*)d_in[3];
    const float* ad1 = (const float*)d_in[4];
    const float* b1  = (const float*)d_in[5];
    const float* W2  = (const float*)d_in[6];
    const float* as2 = (const float*)d_in[7];
    const float* ad2 = (const float*)d_in[8];
    const float* b2  = (const float*)d_in[9];
    float* out = (float*)d_out;
    int E = in_sizes[1] / 2;
    int n4t = (E >> 2) + 1;  // int4 threads + 1 tail thread

    // One-time host-side resources (no device memory involved).
    static cudaStream_t s_csr = nullptr;
    static cudaEvent_t  ev_fork = nullptr, ev_join = nullptr;
    if (s_csr == nullptr) {
        cudaStreamCreateWithFlags(&s_csr, cudaStreamNonBlocking);
        cudaEventCreateWithFlags(&ev_fork, cudaEventDisableTiming);
        cudaEventCreateWithFlags(&ev_join, cudaEventDisableTiming);
    }

    cudaStream_t s0 = 0;  // capture-origin (default) stream

    // Fork: CSR build chain runs on s_csr, independent of gemm1att1.
    cudaEventRecord(ev_fork, s0);
    cudaStreamWaitEvent(s_csr, ev_fork, 0);
    k_zero<<<(N_NODES + 4 + 255) / 256, 256, 0, s_csr>>>();
    k_hist<<<(n4t + 255) / 256, 256, 0, s_csr>>>(ei, E);
    k_scan1<<<SCAN_B, 1024, 0, s_csr>>>();
    k_scan3<<<SCAN_B, 1024, 0, s_csr>>>();
    k_scatter<<<(n4t + 255) / 256, 256, 0, s_csr>>>(ei, E);
    cudaEventRecord(ev_join, s_csr);

    // Main chain on s0 (overlaps with CSR build).
    k_gemm1att1<<<N_NODES / 32, 128, 0, s0>>>(x, W1, as1, ad1);

    // Join: agg1 needs both xl1 (s0) and CSR (s_csr).
    cudaStreamWaitEvent(s0, ev_join, 0);
    k_agg1<<<N_NODES / 8, 256, 0, s0>>>(b1);
    k_gemm2att2<<<N_NODES / 32, 64, 0, s0>>>(W2, as2, ad2);
    k_agg2<<<N_NODES / 8, 256, 0, s0>>>(b2, out);
}